// round 12
// baseline (speedup 1.0000x reference)
#include <cuda_runtime.h>
#include <math.h>

// Problem constants (fixed by reference)
#define BATCH   2
#define NFACES  4096
#define IS      256
#define NPIX    (IS*IS)
#define TPD     16              // tiles per dimension (16x16-pixel tiles)
#define NTILES  (TPD*TPD)       // 256 tiles per batch image
#define RECSZ   24              // floats per precomputed face record (6 x float4)
#define CHUNKF  256             // faces staged in smem per pass (24 KB)
#define NBUCK   8               // depth buckets per tile
#define BUCKCAP 512             // faces per (tile,bucket)
#define BUCKW   (20.5f/8.0f)    // bucket width in z
#define FARV    100.0f
#define NEARV   0.1f

// Scratch (static device globals — no dynamic allocation allowed).
// Face record, 6 float4 rows:
//   q0 = {e0x, e0y, e0c, faceIdx} edge 0->1 coeffs (edge = ex*xp + ey*yp + ec)
//   q1 = {e1x, e1y, e1c, minz}    minz = min vertex z  (z-reject key)
//   q2 = {e2x, e2y, e2c, z2}
//   q3 = {i00, i01, i02, 1/z0}    barycentric inverse row 0 (already / det)
//   q4 = {i10, i11, i12, 1/z1}
//   q5 = {i20, i21, i22, 1/z2}
// Faces in bucket k of a tile satisfy minz >= k*BUCKW  ->  zp >= k*BUCKW.
__device__ float g_rec[BATCH*NFACES*RECSZ];
__device__ int   g_cnt[BATCH*NTILES*NBUCK];  // zero-init; render self-resets each run
__device__ int   g_list[BATCH*NTILES*NBUCK*BUCKCAP];

// One thread per (batch, face): precompute record + bin into overlapped tiles
// (exact conservative corner-max edge test), bucketed by minz.
__global__ void bin_kernel(const float* __restrict__ faces) {
    int gid = blockIdx.x*blockDim.x + threadIdx.x;
    if (gid >= BATCH*NFACES) return;
    int b = gid / NFACES;
    int f = gid - b*NFACES;

    const float* fp = faces + (size_t)gid*9;
    float x0=fp[0], y0=fp[1], z0=fp[2];
    float x1=fp[3], y1=fp[4], z1=fp[5];
    float x2=fp[6], y2=fp[7], z2=fp[8];

    float det  = x2*(y0-y1) + x0*(y1-y2) + x1*(y2-y0);
    float detc = (det >= 0.f) ? fmaxf(det, 1e-10f) : fminf(det, -1e-10f);
    float rdet = __fdividef(1.f, detc);
    float minz = fminf(z0, fminf(z1, z2));

    // Edge coefficients: edge(a->b) at (xp,yp) = ex*xp + ey*yp + ec
    float a0, b0c, c0, a1, b1c, c1, a2, b2c, c2;
    { float dX=x1-x0, dY=y1-y0; a0=-dY; b0c=dX; c0=x0*dY - y0*dX; }
    { float dX=x2-x1, dY=y2-y1; a1=-dY; b1c=dX; c1=x1*dY - y1*dX; }
    { float dX=x0-x2, dY=y0-y2; a2=-dY; b2c=dX; c2=x2*dY - y2*dX; }

    float* r = g_rec + (size_t)gid*RECSZ;
    r[0]=a0; r[1]=b0c; r[2]=c0; r[3]=__int_as_float(f);
    r[4]=a1; r[5]=b1c; r[6]=c1; r[7]=minz;
    r[8]=a2; r[9]=b2c; r[10]=c2; r[11]=z2;
    r[12]=(y1-y2)*rdet; r[13]=(x2-x1)*rdet; r[14]=(x1*y2-x2*y1)*rdet; r[15]=__fdividef(1.f,z0);
    r[16]=(y2-y0)*rdet; r[17]=(x0-x2)*rdet; r[18]=(x2*y0-x0*y2)*rdet; r[19]=__fdividef(1.f,z1);
    r[20]=(y0-y1)*rdet; r[21]=(x1-x0)*rdet; r[22]=(x0*y1-x1*y0)*rdet; r[23]=__fdividef(1.f,z2);

    // Winding cull: e0+e1+e2 == det identically -> all-edges>=0 impossible if det<0.
    if (det <= 0.f) return;

    // Depth bucket: k = floor(minz / W) clamped -> faces in bucket k have minz >= k*W.
    int kb = (int)(fmaxf(minz, 0.f) * (1.0f/BUCKW));
    kb = min(kb, NBUCK-1);

    // Conservative pixel bbox. xp(ix) = (2*ix+1-256)/256, yp(row) = (255-2*row)/256.
    float xmn = fminf(x0, fminf(x1,x2)), xmx = fmaxf(x0, fmaxf(x1,x2));
    float ymn = fminf(y0, fminf(y1,y2)), ymx = fmaxf(y0, fmaxf(y1,y2));
    int ix0 = (int)floorf((256.f*xmn + 255.f)*0.5f) - 1;
    int ix1 = (int)ceilf ((256.f*xmx + 255.f)*0.5f) + 1;
    int iy0 = (int)floorf((255.f - 256.f*ymx)*0.5f) - 1;
    int iy1 = (int)ceilf ((255.f - 256.f*ymn)*0.5f) + 1;
    if (ix1 < 0 || ix0 > IS-1 || iy1 < 0 || iy0 > IS-1) return;
    ix0 = max(ix0, 0); ix1 = min(ix1, IS-1);
    iy0 = max(iy0, 0); iy1 = min(iy1, IS-1);

    int tx0 = ix0 >> 4, tx1 = ix1 >> 4;
    int ty0 = iy0 >> 4, ty1 = iy1 >> 4;
    for (int ty = ty0; ty <= ty1; ty++) {
        // Pixel-center y range of this tile row (yp decreases with py).
        float yhi = (255.f - 32.f*(float)ty) * (1.f/256.f);
        float ylo = (225.f - 32.f*(float)ty) * (1.f/256.f);
        for (int tx = tx0; tx <= tx1; tx++) {
            float xlo = (32.f*(float)tx - 255.f) * (1.f/256.f);
            float xhi = (32.f*(float)tx - 225.f) * (1.f/256.f);
            // Max of each edge over the tile's pixel-center rect (sign-selected corner).
            float m0 = fmaf(a0, (a0>=0.f)?xhi:xlo, fmaf(b0c, (b0c>=0.f)?yhi:ylo, c0));
            float m1 = fmaf(a1, (a1>=0.f)?xhi:xlo, fmaf(b1c, (b1c>=0.f)?yhi:ylo, c1));
            float m2 = fmaf(a2, (a2>=0.f)?xhi:xlo, fmaf(b2c, (b2c>=0.f)?yhi:ylo, c2));
            if (m0 < -1e-6f || m1 < -1e-6f || m2 < -1e-6f) continue;

            int t = (b*NTILES + ty*TPD + tx)*NBUCK + kb;
            int pos = atomicAdd(&g_cnt[t], 1);
            if (pos < BUCKCAP)
                g_list[(size_t)t*BUCKCAP + pos] = f;
        }
    }
}

// Fused raster + shade. Grid (NTILES, BATCH), 512 threads = TWO threads per
// pixel of the 16x16 tile (interleaved halves of each bucket list; merge at end).
// Buckets processed in ascending minz order; block-uniform early exit once every
// thread's bZ beats the bucket's z lower bound.
__global__ void __launch_bounds__(512) render_kernel(
        const float* __restrict__ tex, float* __restrict__ out) {
    __shared__ float4 s_rec[CHUNKF*6];
    __shared__ int    s_cnt[NBUCK];
    __shared__ float  s_z[512];
    __shared__ int    s_f[512];

    int tile = blockIdx.x;
    int b    = blockIdx.y;
    int tid  = threadIdx.x;
    int pid  = tid & 255;            // pixel id within tile
    int half = tid >> 8;             // which half of each bucket list
    int tx = tile & (TPD-1), ty = tile >> 4;
    int lx = pid & 15, ly = pid >> 4;
    int px = (tx<<4) + lx, py = (ty<<4) + ly;

    float xp =  (2.f*(float)px + 1.f - (float)IS) * (1.f/(float)IS);
    float yp = -(2.f*(float)py + 1.f - (float)IS) * (1.f/(float)IS);

    int cidx = b*NTILES + tile;
    if (tid < NBUCK) {
        int c = g_cnt[cidx*NBUCK + tid];
        s_cnt[tid] = min(c, BUCKCAP);
        g_cnt[cidx*NBUCK + tid] = 0;        // restore zero invariant for next run
    }
    __syncthreads();

    const float* recb = g_rec + (size_t)b*NFACES*RECSZ;

    float bZ = FARV;
    int   bF = -1;
    float zGuard = FARV * 1.00001f;         // conservative reject threshold

    for (int kb = 0; kb < NBUCK; kb++) {
        // Faces in bucket kb have minz >= kb*BUCKW, hence zp >= kb*BUCKW.
        // If every thread's current best already beats that bound, no later
        // bucket can change any pixel: exit. (Block-uniform -> safe with syncs.)
        int allDone = __syncthreads_and(zGuard < (float)kb * BUCKW);
        if (allDone) break;
        int cnt = s_cnt[kb];
        if (cnt == 0) continue;
        const int* list = g_list + (size_t)(cidx*NBUCK + kb)*BUCKCAP;

        for (int base = 0; base < cnt; base += CHUNKF) {
            int n  = min(CHUNKF, cnt - base);
            int ne = n*6;
            __syncthreads();                // previous chunk fully consumed
            for (int e = tid; e < ne; e += 512) {
                int i = e/6, j = e - i*6;
                int f = __ldg(list + base + i);
                s_rec[e] = __ldg((const float4*)(recb + (size_t)f*RECSZ) + j);
            }
            __syncthreads();

            for (int i = half; i < n; i += 2) {   // interleaved halves
                // Per-face z-reject: zp >= minz (harmonic mean property).
                float4 p1 = s_rec[i*6+1];         // {e1x, e1y, e1c, minz}
                if (p1.w > zGuard) continue;

                float4 p0 = s_rec[i*6+0], p2 = s_rec[i*6+2];
                float e0 = fmaf(p0.x, xp, fmaf(p0.y, yp, p0.z));
                float e1 = fmaf(p1.x, xp, fmaf(p1.y, yp, p1.z));
                float e2 = fmaf(p2.x, xp, fmaf(p2.y, yp, p2.z));
                if (!(e0 >= 0.f && e1 >= 0.f && e2 >= 0.f)) continue;

                float4 q3 = s_rec[i*6+3], q4 = s_rec[i*6+4], q5 = s_rec[i*6+5];
                float w0 = __saturatef(fmaf(q3.x, xp, fmaf(q3.y, yp, q3.z)));
                float w1 = __saturatef(fmaf(q4.x, xp, fmaf(q4.y, yp, q4.z)));
                float w2 = __saturatef(fmaf(q5.x, xp, fmaf(q5.y, yp, q5.z)));
                float ws = fmaxf(w0 + w1 + w2, 1e-10f);
                // zp = ws / sum(w * 1/z)  (== reference's normalized form)
                float sden = fmaf(w0, q3.w, fmaf(w1, q4.w, w2*q5.w));
                float zp = __fdividef(ws, sden); // sden<=0 -> inf -> fails range test
                if (zp > NEARV && zp < FARV) {
                    int fc = __float_as_int(p0.w);
                    if (zp < bZ || (zp == bZ && (unsigned)fc < (unsigned)bF)) {
                        bZ = zp; bF = fc;
                        zGuard = bZ * 1.00001f;
                    }
                }
            }
        }
    }

    // Merge the two halves' candidates for each pixel (disjoint subsets, strict
    // compare -> reference first-index tie semantics preserved).
    __syncthreads();
    s_z[tid] = bZ; s_f[tid] = bF;
    __syncthreads();
    if (tid >= 256) return;
    {
        float oZ = s_z[tid + 256]; int oF = s_f[tid + 256];
        if (oZ < bZ || (oZ == bZ && (unsigned)oF < (unsigned)bF)) { bZ = oZ; bF = oF; }
    }

    // Shade: recompute winner's weights from its record (L2-hit), trilinear sample.
    float cr = 0.f, cg = 0.f, cb = 0.f, alpha = 0.f;
    if (bF >= 0) {
        alpha = 1.f;
        const float4* R = (const float4*)(recb + (size_t)bF*RECSZ);
        float4 q3 = __ldg(R+3), q4 = __ldg(R+4), q5 = __ldg(R+5);
        float w0 = __saturatef(fmaf(q3.x, xp, fmaf(q3.y, yp, q3.z)));
        float w1 = __saturatef(fmaf(q4.x, xp, fmaf(q4.y, yp, q4.z)));
        float w2 = __saturatef(fmaf(q5.x, xp, fmaf(q5.y, yp, q5.z)));
        float ws = fmaxf(w0 + w1 + w2, 1e-10f);
        float inws = __fdividef(1.f, ws);
        float zt = 3.f * bZ;                                   // (T-1) * zp
        float t0 = fminf(fmaxf(w0*inws * zt * q3.w, 0.f), 2.999f);
        float t1 = fminf(fmaxf(w1*inws * zt * q4.w, 0.f), 2.999f);
        float t2 = fminf(fmaxf(w2*inws * zt * q5.w, 0.f), 2.999f);
        int i0 = (int)t0, i1 = (int)t1, i2 = (int)t2;          // t>=0: trunc==floor
        float f0 = t0-(float)i0, f1 = t1-(float)i1, f2 = t2-(float)i2;
        float a0 = 1.f-f0, a1 = 1.f-f1, a2 = 1.f-f2;
        const float* tb = tex + (size_t)(b*NFACES + bF)*192;   // 4*4*4*3
        #pragma unroll
        for (int pn = 0; pn < 8; pn++) {
            int c0 = pn & 1, c1 = (pn>>1) & 1, c2 = (pn>>2) & 1;
            float wc = (c0 ? f0 : a0) * (c1 ? f1 : a1) * (c2 ? f2 : a2);
            int lin = ((i0+c0)*4 + (i1+c1))*4 + (i2+c2);
            const float* tp = tb + lin*3;
            cr = fmaf(wc, __ldg(tp+0), cr);
            cg = fmaf(wc, __ldg(tp+1), cg);
            cb = fmaf(wc, __ldg(tp+2), cb);
        }
    }

    // Output layout: rgb (B,256,256,3), then alpha (B,256,256), then zp (B,256,256).
    size_t p = (size_t)b*NPIX + (size_t)py*IS + px;
    out[p*3 + 0] = cr;
    out[p*3 + 1] = cg;
    out[p*3 + 2] = cb;
    out[(size_t)BATCH*NPIX*3 + p] = alpha;
    out[(size_t)BATCH*NPIX*4 + p] = bZ;
}

extern "C" void kernel_launch(void* const* d_in, const int* in_sizes, int n_in,
                              void* d_out, int out_size) {
    const float* faces = (const float*)d_in[0];     // (2, 4096, 3, 3) f32
    const float* tex   = (const float*)d_in[1];     // (2, 4096, 4, 4, 4, 3) f32
    float* out = (float*)d_out;                     // 655360 f32: rgb | alpha | zp

    bin_kernel<<<64, 128>>>(faces);
    render_kernel<<<dim3(NTILES, BATCH), 512>>>(tex, out);
}

// round 14
// speedup vs baseline: 1.1826x; 1.1826x over previous
#include <cuda_runtime.h>
#include <math.h>

// Problem constants (fixed by reference)
#define BATCH   2
#define NFACES  4096
#define IS      256
#define NPIX    (IS*IS)
#define TPD     16              // tiles per dimension (16x16-pixel tiles)
#define NTILES  (TPD*TPD)       // 256 tiles per batch image
#define RECSZ   24              // floats per precomputed face record (6 x float4)
#define CHUNKF  256             // faces staged in smem per pass (24 KB)
#define LISTCAP 2048            // faces per (tile,class) list
#define NEARTH  3.0f            // minz threshold separating near/far class
#define FARV    100.0f
#define NEARV   0.1f

// Scratch (static device globals — no dynamic allocation allowed).
// Face record, 6 float4 rows:
//   q0 = {e0x, e0y, e0c, faceIdx} edge 0->1 coeffs (edge = ex*xp + ey*yp + ec)
//   q1 = {e1x, e1y, e1c, minz}    minz = min vertex z  (z-reject key)
//   q2 = {e2x, e2y, e2c, z2}
//   q3 = {i00, i01, i02, 1/z0}    barycentric inverse row 0 (already / det)
//   q4 = {i10, i11, i12, 1/z1}
//   q5 = {i20, i21, i22, 1/z2}
// Two lists per tile: class 0 = near (minz < NEARTH), class 1 = far.
__device__ float g_rec[BATCH*NFACES*RECSZ];
__device__ int   g_cnt[BATCH*NTILES*2];      // zero-init; render self-resets each run
__device__ int   g_list[BATCH*NTILES*2*LISTCAP];

// One thread per (batch, face): precompute record + bin into overlapped tiles
// (exact conservative corner-max edge test), classed by minz.
__global__ void bin_kernel(const float* __restrict__ faces) {
    int gid = blockIdx.x*blockDim.x + threadIdx.x;
    if (gid >= BATCH*NFACES) return;
    int b = gid / NFACES;
    int f = gid - b*NFACES;

    const float* fp = faces + (size_t)gid*9;
    float x0=fp[0], y0=fp[1], z0=fp[2];
    float x1=fp[3], y1=fp[4], z1=fp[5];
    float x2=fp[6], y2=fp[7], z2=fp[8];

    float det  = x2*(y0-y1) + x0*(y1-y2) + x1*(y2-y0);
    float detc = (det >= 0.f) ? fmaxf(det, 1e-10f) : fminf(det, -1e-10f);
    float rdet = __fdividef(1.f, detc);
    float minz = fminf(z0, fminf(z1, z2));

    // Edge coefficients: edge(a->b) at (xp,yp) = ex*xp + ey*yp + ec
    float a0, b0c, c0, a1, b1c, c1, a2, b2c, c2;
    { float dX=x1-x0, dY=y1-y0; a0=-dY; b0c=dX; c0=x0*dY - y0*dX; }
    { float dX=x2-x1, dY=y2-y1; a1=-dY; b1c=dX; c1=x1*dY - y1*dX; }
    { float dX=x0-x2, dY=y0-y2; a2=-dY; b2c=dX; c2=x2*dY - y2*dX; }

    float* r = g_rec + (size_t)gid*RECSZ;
    r[0]=a0; r[1]=b0c; r[2]=c0; r[3]=__int_as_float(f);
    r[4]=a1; r[5]=b1c; r[6]=c1; r[7]=minz;
    r[8]=a2; r[9]=b2c; r[10]=c2; r[11]=z2;
    r[12]=(y1-y2)*rdet; r[13]=(x2-x1)*rdet; r[14]=(x1*y2-x2*y1)*rdet; r[15]=__fdividef(1.f,z0);
    r[16]=(y2-y0)*rdet; r[17]=(x0-x2)*rdet; r[18]=(x2*y0-x0*y2)*rdet; r[19]=__fdividef(1.f,z1);
    r[20]=(y0-y1)*rdet; r[21]=(x1-x0)*rdet; r[22]=(x0*y1-x1*y0)*rdet; r[23]=__fdividef(1.f,z2);

    // Winding cull: e0+e1+e2 == det identically -> all-edges>=0 impossible if det<0.
    if (det <= 0.f) return;

    int cls = (minz < NEARTH) ? 0 : 1;

    // Conservative pixel bbox. xp(ix) = (2*ix+1-256)/256, yp(row) = (255-2*row)/256.
    float xmn = fminf(x0, fminf(x1,x2)), xmx = fmaxf(x0, fmaxf(x1,x2));
    float ymn = fminf(y0, fminf(y1,y2)), ymx = fmaxf(y0, fmaxf(y1,y2));
    int ix0 = (int)floorf((256.f*xmn + 255.f)*0.5f) - 1;
    int ix1 = (int)ceilf ((256.f*xmx + 255.f)*0.5f) + 1;
    int iy0 = (int)floorf((255.f - 256.f*ymx)*0.5f) - 1;
    int iy1 = (int)ceilf ((255.f - 256.f*ymn)*0.5f) + 1;
    if (ix1 < 0 || ix0 > IS-1 || iy1 < 0 || iy0 > IS-1) return;
    ix0 = max(ix0, 0); ix1 = min(ix1, IS-1);
    iy0 = max(iy0, 0); iy1 = min(iy1, IS-1);

    int tx0 = ix0 >> 4, tx1 = ix1 >> 4;
    int ty0 = iy0 >> 4, ty1 = iy1 >> 4;
    for (int ty = ty0; ty <= ty1; ty++) {
        // Pixel-center y range of this tile row (yp decreases with py).
        float yhi = (255.f - 32.f*(float)ty) * (1.f/256.f);
        float ylo = (225.f - 32.f*(float)ty) * (1.f/256.f);
        for (int tx = tx0; tx <= tx1; tx++) {
            float xlo = (32.f*(float)tx - 255.f) * (1.f/256.f);
            float xhi = (32.f*(float)tx - 225.f) * (1.f/256.f);
            // Max of each edge over the tile's pixel-center rect (sign-selected corner).
            float m0 = fmaf(a0, (a0>=0.f)?xhi:xlo, fmaf(b0c, (b0c>=0.f)?yhi:ylo, c0));
            float m1 = fmaf(a1, (a1>=0.f)?xhi:xlo, fmaf(b1c, (b1c>=0.f)?yhi:ylo, c1));
            float m2 = fmaf(a2, (a2>=0.f)?xhi:xlo, fmaf(b2c, (b2c>=0.f)?yhi:ylo, c2));
            if (m0 < -1e-6f || m1 < -1e-6f || m2 < -1e-6f) continue;

            int t = (b*NTILES + ty*TPD + tx)*2 + cls;
            int pos = atomicAdd(&g_cnt[t], 1);
            if (pos < LISTCAP)
                g_list[(size_t)t*LISTCAP + pos] = f;
        }
    }
}

// Fused raster + shade. Grid (NTILES, BATCH), 512 threads = TWO threads per
// pixel of the 16x16 tile (interleaved halves; merge at end). Near and far
// lists are concatenated at staging time (near first), so zGuard tightens in
// the first few iterations and the per-face warp-level z-reject skips the far
// tail at ~4 instructions per face.
__global__ void __launch_bounds__(512) render_kernel(
        const float* __restrict__ tex, float* __restrict__ out) {
    __shared__ float4 s_rec[CHUNKF*6];
    __shared__ float  s_z[512];
    __shared__ int    s_f[512];

    int tile = blockIdx.x;
    int b    = blockIdx.y;
    int tid  = threadIdx.x;
    int pid  = tid & 255;            // pixel id within tile
    int half = tid >> 8;             // which half of the face list
    int tx = tile & (TPD-1), ty = tile >> 4;
    int lx = pid & 15, ly = pid >> 4;
    int px = (tx<<4) + lx, py = (ty<<4) + ly;

    float xp =  (2.f*(float)px + 1.f - (float)IS) * (1.f/(float)IS);
    float yp = -(2.f*(float)py + 1.f - (float)IS) * (1.f/(float)IS);

    int cidx = b*NTILES + tile;
    int n0 = min(g_cnt[cidx*2+0], LISTCAP);     // near
    int n1 = min(g_cnt[cidx*2+1], LISTCAP);     // far
    int cnt = n0 + n1;
    __syncthreads();                            // all reads of g_cnt before reset
    if (tid == 0) { g_cnt[cidx*2+0] = 0; g_cnt[cidx*2+1] = 0; }

    const int* list0 = g_list + (size_t)(cidx*2+0)*LISTCAP;
    const int* list1 = g_list + (size_t)(cidx*2+1)*LISTCAP;
    const float* recb = g_rec + (size_t)b*NFACES*RECSZ;

    float bZ = FARV;
    int   bF = -1;
    float zGuard = FARV * 1.00001f;             // conservative reject threshold

    for (int base = 0; base < cnt; base += CHUNKF) {
        int n  = min(CHUNKF, cnt - base);
        int ne = n*6;
        __syncthreads();                        // previous chunk fully consumed
        for (int e = tid; e < ne; e += 512) {
            int i = e/6, j = e - i*6;
            int gi = base + i;                  // global position in concat order
            int f = (gi < n0) ? __ldg(list0 + gi) : __ldg(list1 + gi - n0);
            s_rec[e] = __ldg((const float4*)(recb + (size_t)f*RECSZ) + j);
        }
        __syncthreads();

        for (int i = half; i < n; i += 2) {     // interleaved halves
            // Per-face z-reject: zp >= minz (harmonic mean of vertex z with
            // clipped+renormalized weights), so minz > zGuard can never win.
            float4 p1 = s_rec[i*6+1];           // {e1x, e1y, e1c, minz}
            if (p1.w > zGuard) continue;

            float4 p0 = s_rec[i*6+0], p2 = s_rec[i*6+2];
            float e0 = fmaf(p0.x, xp, fmaf(p0.y, yp, p0.z));
            float e1 = fmaf(p1.x, xp, fmaf(p1.y, yp, p1.z));
            float e2 = fmaf(p2.x, xp, fmaf(p2.y, yp, p2.z));
            if (!(e0 >= 0.f && e1 >= 0.f && e2 >= 0.f)) continue;

            float4 q3 = s_rec[i*6+3], q4 = s_rec[i*6+4], q5 = s_rec[i*6+5];
            float w0 = __saturatef(fmaf(q3.x, xp, fmaf(q3.y, yp, q3.z)));
            float w1 = __saturatef(fmaf(q4.x, xp, fmaf(q4.y, yp, q4.z)));
            float w2 = __saturatef(fmaf(q5.x, xp, fmaf(q5.y, yp, q5.z)));
            float ws = fmaxf(w0 + w1 + w2, 1e-10f);
            // zp = ws / sum(w * 1/z)  (== reference's normalized form)
            float sden = fmaf(w0, q3.w, fmaf(w1, q4.w, w2*q5.w));
            float zp = __fdividef(ws, sden);    // sden<=0 -> inf -> fails range test
            if (zp > NEARV && zp < FARV) {
                int fc = __float_as_int(p0.w);
                if (zp < bZ || (zp == bZ && (unsigned)fc < (unsigned)bF)) {
                    bZ = zp; bF = fc;
                    zGuard = bZ * 1.00001f;
                }
            }
        }
    }

    // Merge the two halves' candidates for each pixel (disjoint subsets, strict
    // compare -> reference first-index tie semantics preserved).
    __syncthreads();
    s_z[tid] = bZ; s_f[tid] = bF;
    __syncthreads();
    if (tid >= 256) return;
    {
        float oZ = s_z[tid + 256]; int oF = s_f[tid + 256];
        if (oZ < bZ || (oZ == bZ && (unsigned)oF < (unsigned)bF)) { bZ = oZ; bF = oF; }
    }

    // Shade: recompute winner's weights from its record (L2-hit), trilinear sample.
    float cr = 0.f, cg = 0.f, cb = 0.f, alpha = 0.f;
    if (bF >= 0) {
        alpha = 1.f;
        const float4* R = (const float4*)(recb + (size_t)bF*RECSZ);
        float4 q3 = __ldg(R+3), q4 = __ldg(R+4), q5 = __ldg(R+5);
        float w0 = __saturatef(fmaf(q3.x, xp, fmaf(q3.y, yp, q3.z)));
        float w1 = __saturatef(fmaf(q4.x, xp, fmaf(q4.y, yp, q4.z)));
        float w2 = __saturatef(fmaf(q5.x, xp, fmaf(q5.y, yp, q5.z)));
        float ws = fmaxf(w0 + w1 + w2, 1e-10f);
        float inws = __fdividef(1.f, ws);
        float zt = 3.f * bZ;                                   // (T-1) * zp
        float t0 = fminf(fmaxf(w0*inws * zt * q3.w, 0.f), 2.999f);
        float t1 = fminf(fmaxf(w1*inws * zt * q4.w, 0.f), 2.999f);
        float t2 = fminf(fmaxf(w2*inws * zt * q5.w, 0.f), 2.999f);
        int i0 = (int)t0, i1 = (int)t1, i2 = (int)t2;          // t>=0: trunc==floor
        float f0 = t0-(float)i0, f1 = t1-(float)i1, f2 = t2-(float)i2;
        float a0 = 1.f-f0, a1 = 1.f-f1, a2 = 1.f-f2;
        const float* tb = tex + (size_t)(b*NFACES + bF)*192;   // 4*4*4*3
        #pragma unroll
        for (int pn = 0; pn < 8; pn++) {
            int c0 = pn & 1, c1 = (pn>>1) & 1, c2 = (pn>>2) & 1;
            float wc = (c0 ? f0 : a0) * (c1 ? f1 : a1) * (c2 ? f2 : a2);
            int lin = ((i0+c0)*4 + (i1+c1))*4 + (i2+c2);
            const float* tp = tb + lin*3;
            cr = fmaf(wc, __ldg(tp+0), cr);
            cg = fmaf(wc, __ldg(tp+1), cg);
            cb = fmaf(wc, __ldg(tp+2), cb);
        }
    }

    // Output layout: rgb (B,256,256,3), then alpha (B,256,256), then zp (B,256,256).
    size_t p = (size_t)b*NPIX + (size_t)py*IS + px;
    out[p*3 + 0] = cr;
    out[p*3 + 1] = cg;
    out[p*3 + 2] = cb;
    out[(size_t)BATCH*NPIX*3 + p] = alpha;
    out[(size_t)BATCH*NPIX*4 + p] = bZ;
}

extern "C" void kernel_launch(void* const* d_in, const int* in_sizes, int n_in,
                              void* d_out, int out_size) {
    const float* faces = (const float*)d_in[0];     // (2, 4096, 3, 3) f32
    const float* tex   = (const float*)d_in[1];     // (2, 4096, 4, 4, 4, 3) f32
    float* out = (float*)d_out;                     // 655360 f32: rgb | alpha | zp

    bin_kernel<<<64, 128>>>(faces);
    render_kernel<<<dim3(NTILES, BATCH), 512>>>(tex, out);
}